// round 8
// baseline (speedup 1.0000x reference)
#include <cuda_runtime.h>
#include <stdint.h>
#include <stddef.h>

// SparkFieldNet single step, bit-matching JAX threefry-2x32 RNG
// (jax_threefry_partitionable scheme).
// Inputs: 0=W[N*N] f32, 1=s[N] f32, 2=M[N] f32, 3=spark_pos[K] i32,
//         4=spark_energy[K] f32, 5=spark_age[K] i32
// Output: concat(pos[K], W[N*N], s[N], M[N], energy[K], age[K]) as float32.

#define N 8192
#define K 256
#define TOPT 32
#define BIT_DEP (1 << 16)
#define BIT_LST (1 << 17)

extern "C" __device__ float __nv_logf(float);

typedef unsigned long long u64;

// ---- device scratch ----
__device__ float g_z0[(size_t)K * N];    // gumbel + (div + 0.8*Mdec)
__device__ float g_gum[(size_t)K * N];   // gumbel
__device__ float g_div[(size_t)K * N];   // (relu(W0[row])+1e-6)/0.3
__device__ float g_col[(size_t)K * N];   // g_col[i][j] = W[j, sp[i]]
__device__ u64   g_top[(size_t)K * TOPT];// per-spark sorted top-32 packed keys
__device__ float g_Ws[N];
__device__ float g_sState[N];
__device__ float g_Mdec[N];
__device__ int   g_forced[N];
__device__ unsigned g_kc0[K], g_kc1[K];
__device__ int   g_explore[K];
__device__ int   g_randpos[K];

// ---------------- Threefry-2x32 (JAX-exact, 20 rounds) ----------------
__device__ __forceinline__ void tf2x32(unsigned k0, unsigned k1,
                                       unsigned x0, unsigned x1,
                                       unsigned& o0, unsigned& o1) {
  unsigned ks2 = k0 ^ k1 ^ 0x1BD11BDAu;
  x0 += k0; x1 += k1;
#define TFR(r) { x0 += x1; x1 = (x1 << (r)) | (x1 >> (32 - (r))); x1 ^= x0; }
  TFR(13) TFR(15) TFR(26) TFR(6)   x0 += k1;  x1 += ks2 + 1u;
  TFR(17) TFR(29) TFR(16) TFR(24)  x0 += ks2; x1 += k0 + 2u;
  TFR(13) TFR(15) TFR(26) TFR(6)   x0 += k0;  x1 += k1 + 3u;
  TFR(17) TFR(29) TFR(16) TFR(24)  x0 += k1;  x1 += ks2 + 4u;
  TFR(13) TFR(15) TFR(26) TFR(6)   x0 += ks2; x1 += k0 + 5u;
#undef TFR
  o0 = x0; o1 = x1;
}

__device__ __forceinline__ void keypair(unsigned k0, unsigned k1, unsigned i,
                                        unsigned& o0, unsigned& o1) {
  tf2x32(k0, k1, 0u, i, o0, o1);
}

__device__ __forceinline__ unsigned bits32(unsigned k0, unsigned k1, unsigned j) {
  unsigned o0, o1;
  tf2x32(k0, k1, 0u, j, o0, o1);
  return o0 ^ o1;
}

__device__ __forceinline__ float f01(unsigned b) {
  return __fadd_rn(__uint_as_float((b >> 9) | 0x3f800000u), -1.0f);
}

__device__ __forceinline__ u64 packz(float z, int j) {
  unsigned zu = __float_as_uint(z);
  zu = (zu & 0x80000000u) ? ~zu : (zu | 0x80000000u);
  return ((u64)zu << 32) | (unsigned)(N - 1 - j);   // tie -> smaller index wins
}

// XLA ErfInv f32 polynomial (Giles)
__device__ __forceinline__ float erfinv_xla(float x) {
  float w = -log1pf(-__fmul_rn(x, x));
  float p;
  if (w < 5.0f) {
    w = w - 2.5f;
    p = 2.81022636e-08f;
    p = fmaf(p, w, 3.43273939e-07f);
    p = fmaf(p, w, -3.5233877e-06f);
    p = fmaf(p, w, -4.39150654e-06f);
    p = fmaf(p, w, 0.00021858087f);
    p = fmaf(p, w, -0.00125372503f);
    p = fmaf(p, w, -0.00417768164f);
    p = fmaf(p, w, 0.246640727f);
    p = fmaf(p, w, 1.50140941f);
  } else {
    w = sqrtf(w) - 3.0f;
    p = -0.000200214257f;
    p = fmaf(p, w, 0.000100950558f);
    p = fmaf(p, w, 0.00134934322f);
    p = fmaf(p, w, -0.00367342844f);
    p = fmaf(p, w, 0.00573950773f);
    p = fmaf(p, w, -0.0076224613f);
    p = fmaf(p, w, 0.00943887047f);
    p = fmaf(p, w, 1.00167406f);
    p = fmaf(p, w, 2.83297682f);
  }
  return p * x;
}

// ---------------- kInit ----------------
__global__ void __launch_bounds__(256) kInit(const int* __restrict__ spark_pos,
                                             const int* __restrict__ spark_age) {
  int t = threadIdx.x;
  for (int j = t; j < N; j += 256) g_forced[j] = 0;
  __syncthreads();

  const unsigned B0 = 0u, B1 = 42u;
  unsigned kexp0, kexp1, krand0, krand1, kcat0, kcat1;
  keypair(B0, B1, 1u, kexp0, kexp1);
  keypair(B0, B1, 2u, krand0, krand1);
  keypair(B0, B1, 3u, kcat0, kcat1);

  int i = t;
  unsigned ke0, ke1;
  keypair(kexp0, kexp1, (unsigned)i, ke0, ke1);
  g_explore[i] = (f01(bits32(ke0, ke1, 0u)) < 0.05f) ? 1 : 0;
  unsigned kr0, kr1, k20, k21;
  keypair(krand0, krand1, (unsigned)i, kr0, kr1);
  keypair(kr0, kr1, 1u, k20, k21);
  g_randpos[i] = (int)(bits32(k20, k21, 0u) & (unsigned)(N - 1));
  unsigned kc0, kc1;
  keypair(kcat0, kcat1, (unsigned)i, kc0, kc1);
  g_kc0[i] = kc0;
  g_kc1[i] = kc1;
  if (spark_age[i] < 5) g_forced[spark_pos[i]] = 1;
}

// ---------------- kMV ----------------
__global__ void __launch_bounds__(256) kMV(const float* __restrict__ W,
                                           const float* __restrict__ s_in,
                                           float* __restrict__ outW) {
  int r = blockIdx.x;
  const float4* w4 = (const float4*)(W + (size_t)r * N);
  const float4* s4 = (const float4*)s_in;
  float4* o4 = (float4*)(outW + (size_t)r * N);
  float acc = 0.f;
  for (int k = threadIdx.x; k < N / 4; k += 256) {
    float4 w = w4[k];
    float4 sv = s4[k];
    acc += w.x * (sv.x * 0.95f) + w.y * (sv.y * 0.95f)
         + w.z * (sv.z * 0.95f) + w.w * (sv.w * 0.95f);
    float4 o;
    o.x = fminf(fmaxf(__fmul_rn(w.x, 0.999f), -2.f), 2.f);
    o.y = fminf(fmaxf(__fmul_rn(w.y, 0.999f), -2.f), 2.f);
    o.z = fminf(fmaxf(__fmul_rn(w.z, 0.999f), -2.f), 2.f);
    o.w = fminf(fmaxf(__fmul_rn(w.w, 0.999f), -2.f), 2.f);
    o4[k] = o;
  }
  for (int off = 16; off; off >>= 1) acc += __shfl_down_sync(0xffffffffu, acc, off);
  __shared__ float sred[8];
  if ((threadIdx.x & 31) == 0) sred[threadIdx.x >> 5] = acc;
  __syncthreads();
  if (threadIdx.x == 0) {
    float a = 0.f;
    for (int w = 0; w < 8; w++) a += sred[w];
    g_Ws[r] = a;
  }
}

// ---------------- kState ----------------
__device__ __forceinline__ void state_one(int j, unsigned b) {
  const float LO = __int_as_float(0xBF7FFFFF);
  const float SQ2 = __int_as_float(0x3FB504F3);
  float f = f01(b);
  float u = fmaxf(LO, __fadd_rn(__fmul_rn(f, 2.0f), LO));
  float nrm = __fmul_rn(SQ2, erfinv_xla(u));
  float noise = __fmul_rn(0.05f, nrm);
  float x = __fadd_rn(g_Ws[j], noise);
  float s = g_forced[j] ? 1.0f : (1.0f / (1.0f + expf(-x)));
  g_sState[j] = s;
}

__global__ void __launch_bounds__(512) kState(const float* __restrict__ M_in) {
  int t = blockIdx.x * 512 + threadIdx.x;
  const unsigned B0 = 0u, B1 = 42u;
  unsigned n0, n1;
  keypair(B0, B1, 0u, n0, n1);
  state_one(t,        bits32(n0, n1, (unsigned)t));
  state_one(t + 4096, bits32(n0, n1, (unsigned)(t + 4096)));
  g_Mdec[t]        = __fmul_rn(M_in[t], 0.95f);
  g_Mdec[t + 4096] = __fmul_rn(M_in[t + 4096], 0.95f);
}

// ---------------- kGum: gumbels + z0 + top-32 selection + column prefetch ----
__global__ void __launch_bounds__(1024) kGum(const float* __restrict__ W,
                                             const int* __restrict__ spark_pos) {
  extern __shared__ u64 sm_keys[];          // N keys = 64KB
  __shared__ u64 sm_red[32];
  __shared__ u64 sm_win;
  int i = blockIdx.x;
  int row = spark_pos[i];
  unsigned kc0 = g_kc0[i], kc1 = g_kc1[i];
  const float* wrow = W + (size_t)row * N;
  size_t base = (size_t)i * N;
  int tid = threadIdx.x;

  for (int j = tid; j < N; j += 1024) {
    unsigned b = bits32(kc0, kc1, (unsigned)j);
    float u = fmaxf(f01(b), 1.17549435e-38f);
    float g = -__nv_logf(-__nv_logf(u));
    float dv = __fdiv_rn(__fadd_rn(fmaxf(wrow[j], 0.0f), 1e-6f), 0.3f);
    float z0 = __fadd_rn(g, __fadd_rn(dv, __fmul_rn(0.8f, g_Mdec[j])));
    g_gum[base + j] = g;
    g_div[base + j] = dv;
    g_z0[base + j] = z0;
    sm_keys[j] = packz(z0, j);
    g_col[base + j] = W[(size_t)j * N + row];   // column sp[i] prefetch
  }
  __syncthreads();

  u64 tmax = 0;
  #pragma unroll
  for (int t = 0; t < 8; t++) {
    u64 k = sm_keys[tid + t * 1024];
    if (k > tmax) tmax = k;
  }
  for (int rd = 0; rd < TOPT; rd++) {
    u64 v = tmax;
    for (int o = 16; o; o >>= 1) {
      u64 x = __shfl_down_sync(0xffffffffu, v, o);
      if (x > v) v = x;
    }
    if ((tid & 31) == 0) sm_red[tid >> 5] = v;
    __syncthreads();
    if (tid < 32) {
      u64 w = sm_red[tid];
      for (int o = 16; o; o >>= 1) {
        u64 x = __shfl_down_sync(0xffffffffu, w, o);
        if (x > w) w = x;
      }
      if (tid == 0) { sm_win = w; g_top[(size_t)i * TOPT + rd] = w; }
    }
    __syncthreads();
    u64 w = sm_win;
    if (tmax == w) {     // unique owner (keys unique)
      tmax = 0;
      #pragma unroll
      for (int t = 0; t < 8; t++) {
        int j = tid + t * 1024;
        u64 kk = sm_keys[j];
        if (kk == w) { sm_keys[j] = 0; kk = 0; }
        if (kk > tmax) tmax = kk;
      }
    }
  }
}

// ---------------- kScan: 256 serial iterations, warp-0 inner loop ----------
// dyn smem: s[N] M[N] pnew[N] c[N] + dlist[768] + per-spark arrays + results
#define SMEM_SCAN (4 * N * 4 + 768 * 4 + 8 * K * 4 + 64)

__global__ void __launch_bounds__(1024) kScan(const int* __restrict__ sp,
                                              const float* __restrict__ se,
                                              const int* __restrict__ sa,
                                              float* __restrict__ out) {
  extern __shared__ __align__(16) unsigned char smraw[];
  float* s_sh = (float*)smraw;
  float* M_sh = s_sh + N;
  float* pnew = M_sh + N;
  int*   c_sh = (int*)(pnew + N);
  int*   dlist = c_sh + N;            // 768
  int*   sp_sh = dlist + 768;         // K
  float* se_sh = (float*)(sp_sh + K); // K
  int*   sa_sh = (int*)(se_sh + K);   // K
  int*   ex_sh = sa_sh + K;           // K
  int*   rp_sh = ex_sh + K;           // K
  int*   res_pos = rp_sh + K;         // K
  float* res_e = (float*)(res_pos + K);
  int*   res_age = (int*)(res_e + K);

  int tid = threadIdx.x;
  for (int j = tid; j < N; j += 1024) {
    s_sh[j] = g_sState[j];
    M_sh[j] = g_Mdec[j];
    c_sh[j] = 0;
    pnew[j] = 0.f;
  }
  if (tid < K) {
    sp_sh[tid] = sp[tid];
    se_sh[tid] = se[tid];
    sa_sh[tid] = sa[tid];
    ex_sh[tid] = g_explore[tid];
    rp_sh[tid] = g_randpos[tid];
  }
  __syncthreads();

  if (tid < 32) {
    const unsigned FULL = 0xffffffffu;
    int lane = tid;
    int nd = 0;
    for (int i = 0; i < K; i++) {
      int r = sp_sh[i];
      size_t base = (size_t)i * N;
      u64 cnd = g_top[(size_t)i * TOPT + lane];   // sorted desc by packed key

      // exact recompute over dirty positions
      u64 dmax = 0;
      for (int m = lane; m < nd; m += 32) {
        int idx = dlist[m];
        int c = c_sh[idx];
        float dv;
        if ((c & 0xffff) == (r + 1))
          dv = __fdiv_rn(__fadd_rn(fmaxf(pnew[idx], 0.0f), 1e-6f), 0.3f);
        else
          dv = g_div[base + idx];
        float z = __fadd_rn(g_gum[base + idx],
                            __fadd_rn(dv, __fmul_rn(0.8f, M_sh[idx])));
        u64 pk = packz(z, idx);
        if (pk > dmax) dmax = pk;
      }
      for (int o = 16; o; o >>= 1) {
        u64 v = __shfl_xor_sync(FULL, dmax, o);
        if (v > dmax) dmax = v;
      }

      // best clean candidate = first non-dirty entry of the sorted top list
      int cidx = (N - 1) - (int)(unsigned)(cnd & 0xffffffffu);
      bool clean = !(c_sh[cidx] & BIT_LST);
      unsigned mk = __ballot_sync(FULL, clean);
      u64 best;
      if (mk) {
        best = __shfl_sync(FULL, cnd, __ffs(mk) - 1);
        if (dmax > best) best = dmax;
      } else {
        u64 last = __shfl_sync(FULL, cnd, TOPT - 1);
        if (dmax > last) {
          best = dmax;   // clean max <= last < dmax
        } else {
          // fallback: exact full-row warp scan (never expected in practice)
          u64 fb = 0;
          for (int j = lane; j < N; j += 32) {
            int c = c_sh[j];
            float z;
            bool pat = (c & 0xffff) == (r + 1);
            if ((c & BIT_DEP) || pat) {
              float dv = pat
                ? __fdiv_rn(__fadd_rn(fmaxf(pnew[j], 0.0f), 1e-6f), 0.3f)
                : g_div[base + j];
              z = __fadd_rn(g_gum[base + j],
                            __fadd_rn(dv, __fmul_rn(0.8f, M_sh[j])));
            } else {
              z = g_z0[base + j];
            }
            u64 pk = packz(z, j);
            if (pk > fb) fb = pk;
          }
          for (int o = 16; o; o >>= 1) {
            u64 v = __shfl_xor_sync(FULL, fb, o);
            if (v > fb) fb = v;
          }
          best = fb;
        }
      }

      if (lane == 0) {
        int cat = (N - 1) - (int)(unsigned)(best & 0xffffffffu);
        int nxt = ex_sh[i] ? rp_sh[i] : cat;
        int prev = r;
        // edge update
        int cp = c_sh[prev];
        float wold = ((cp & 0xffff) == (nxt + 1)) ? pnew[prev]
                                                  : g_col[base + nxt];
        pnew[prev] = __fadd_rn(__fmul_rn(wold, 0.95f),
                               __fmul_rn(s_sh[prev], 0.05f));
        int ncp = (cp & ~0xffff) | (nxt + 1);
        if (!(cp & BIT_LST)) { dlist[nd++] = prev; ncp |= BIT_LST; }
        c_sh[prev] = ncp;
        // pheromone deposit (read c_sh[nxt] AFTER prev write: nxt may == prev)
        int cn = c_sh[nxt];
        M_sh[nxt] = __fadd_rn(M_sh[nxt], 0.2f);
        int ncn = cn | BIT_DEP;
        if (!(cn & BIT_LST)) { dlist[nd++] = nxt; ncn |= BIT_LST; }
        c_sh[nxt] = ncn;
        // energy / state / age
        float e = __fmul_rn(se_sh[i], 0.98f);
        s_sh[nxt] = e;
        int age = sa_sh[i] + 1;
        int pos = nxt;
        if (e < 0.05f) { pos = i % N; e = 1.0f; age = 0; }
        res_pos[i] = pos;
        res_e[i] = e;
        res_age[i] = age;
      }
      __syncwarp(FULL);
      nd = __shfl_sync(FULL, nd, 0);
    }
  }
  __syncthreads();

  // epilogue: outputs (layout: pos[K], W[N*N], s[N], M[N], energy[K], age[K])
  const size_t OUT_W = K;
  const size_t OUT_S = OUT_W + (size_t)N * N;
  const size_t OUT_M = OUT_S + N;
  const size_t OUT_E = OUT_M + N;
  const size_t OUT_A = OUT_E + K;
  for (int j = tid; j < N; j += 1024) {
    out[OUT_S + j] = s_sh[j];
    out[OUT_M + j] = M_sh[j];
    int c = c_sh[j];
    int prow = c & 0xffff;
    if (prow) {
      size_t idx = (size_t)(prow - 1) * N + (size_t)j;
      out[OUT_W + idx] = fminf(fmaxf(__fmul_rn(pnew[j], 0.999f), -2.f), 2.f);
    }
  }
  for (int i2 = tid; i2 < K; i2 += 1024) {
    out[i2] = (float)res_pos[i2];
    out[OUT_E + i2] = res_e[i2];
    out[OUT_A + i2] = (float)res_age[i2];
  }
}

// ---------------- launch ----------------
extern "C" void kernel_launch(void* const* d_in, const int* in_sizes, int n_in,
                              void* d_out, int out_size) {
  const float* W = (const float*)d_in[0];
  const float* s = (const float*)d_in[1];
  const float* M = (const float*)d_in[2];
  const int* sp = (const int*)d_in[3];
  const float* se = (const float*)d_in[4];
  const int* sa = (const int*)d_in[5];
  float* out = (float*)d_out;

  cudaFuncSetAttribute(kGum, cudaFuncAttributeMaxDynamicSharedMemorySize,
                       N * 8);
  cudaFuncSetAttribute(kScan, cudaFuncAttributeMaxDynamicSharedMemorySize,
                       SMEM_SCAN);

  kInit<<<1, 256>>>(sp, sa);
  kMV<<<N, 256>>>(W, s, out + K);      // out_W starts right after pos[K]
  kState<<<8, 512>>>(M);
  kGum<<<K, 1024, N * 8>>>(W, sp);
  kScan<<<1, 1024, SMEM_SCAN>>>(sp, se, sa, out);
}

// round 9
// speedup vs baseline: 2.4175x; 2.4175x over previous
#include <cuda_runtime.h>
#include <stdint.h>
#include <stddef.h>

// SparkFieldNet single step, bit-matching JAX threefry-2x32 RNG
// (jax_threefry_partitionable scheme).
// Inputs: 0=W[N*N] f32, 1=s[N] f32, 2=M[N] f32, 3=spark_pos[K] i32,
//         4=spark_energy[K] f32, 5=spark_age[K] i32
// Output: concat(pos[K], W[N*N], s[N], M[N], energy[K], age[K]) as float32.

#define N 8192
#define K 256
#define TOPT 32
#define BIT_DEP (1 << 16)
#define BIT_LST (1 << 17)

extern "C" __device__ float __nv_logf(float);

typedef unsigned long long u64;

// ---- device scratch ----
__device__ float2 g_gd[(size_t)K * N];   // {gumbel, div} per spark x pos (16MB)
__device__ float  g_Wc[(size_t)N * 256]; // W[:, 0:256] compact copy (8MB)
__device__ u64    g_top[(size_t)K * TOPT];
__device__ float  g_Ws[N];
__device__ float  g_sState[N];
__device__ float  g_Mdec[N];
__device__ int    g_forced[N];
__device__ unsigned g_kc0[K], g_kc1[K];
__device__ int    g_explore[K];
__device__ int    g_randpos[K];

// ---------------- Threefry-2x32 (JAX-exact, 20 rounds) ----------------
__device__ __forceinline__ void tf2x32(unsigned k0, unsigned k1,
                                       unsigned x0, unsigned x1,
                                       unsigned& o0, unsigned& o1) {
  unsigned ks2 = k0 ^ k1 ^ 0x1BD11BDAu;
  x0 += k0; x1 += k1;
#define TFR(r) { x0 += x1; x1 = (x1 << (r)) | (x1 >> (32 - (r))); x1 ^= x0; }
  TFR(13) TFR(15) TFR(26) TFR(6)   x0 += k1;  x1 += ks2 + 1u;
  TFR(17) TFR(29) TFR(16) TFR(24)  x0 += ks2; x1 += k0 + 2u;
  TFR(13) TFR(15) TFR(26) TFR(6)   x0 += k0;  x1 += k1 + 3u;
  TFR(17) TFR(29) TFR(16) TFR(24)  x0 += k1;  x1 += ks2 + 4u;
  TFR(13) TFR(15) TFR(26) TFR(6)   x0 += ks2; x1 += k0 + 5u;
#undef TFR
  o0 = x0; o1 = x1;
}

__device__ __forceinline__ void keypair(unsigned k0, unsigned k1, unsigned i,
                                        unsigned& o0, unsigned& o1) {
  tf2x32(k0, k1, 0u, i, o0, o1);
}

__device__ __forceinline__ unsigned bits32(unsigned k0, unsigned k1, unsigned j) {
  unsigned o0, o1;
  tf2x32(k0, k1, 0u, j, o0, o1);
  return o0 ^ o1;
}

__device__ __forceinline__ float f01(unsigned b) {
  return __fadd_rn(__uint_as_float((b >> 9) | 0x3f800000u), -1.0f);
}

__device__ __forceinline__ u64 packz(float z, int j) {
  unsigned zu = __float_as_uint(z);
  zu = (zu & 0x80000000u) ? ~zu : (zu | 0x80000000u);
  return ((u64)zu << 32) | (unsigned)(N - 1 - j);   // tie -> smaller index wins
}

__device__ __forceinline__ float divf(float w) {
  return __fdiv_rn(__fadd_rn(fmaxf(w, 0.0f), 1e-6f), 0.3f);
}

__device__ __forceinline__ float zf(float g, float dv, float m) {
  return __fadd_rn(g, __fadd_rn(dv, __fmul_rn(0.8f, m)));
}

// XLA ErfInv f32 polynomial (Giles)
__device__ __forceinline__ float erfinv_xla(float x) {
  float w = -log1pf(-__fmul_rn(x, x));
  float p;
  if (w < 5.0f) {
    w = w - 2.5f;
    p = 2.81022636e-08f;
    p = fmaf(p, w, 3.43273939e-07f);
    p = fmaf(p, w, -3.5233877e-06f);
    p = fmaf(p, w, -4.39150654e-06f);
    p = fmaf(p, w, 0.00021858087f);
    p = fmaf(p, w, -0.00125372503f);
    p = fmaf(p, w, -0.00417768164f);
    p = fmaf(p, w, 0.246640727f);
    p = fmaf(p, w, 1.50140941f);
  } else {
    w = sqrtf(w) - 3.0f;
    p = -0.000200214257f;
    p = fmaf(p, w, 0.000100950558f);
    p = fmaf(p, w, 0.00134934322f);
    p = fmaf(p, w, -0.00367342844f);
    p = fmaf(p, w, 0.00573950773f);
    p = fmaf(p, w, -0.0076224613f);
    p = fmaf(p, w, 0.00943887047f);
    p = fmaf(p, w, 1.00167406f);
    p = fmaf(p, w, 2.83297682f);
  }
  return p * x;
}

// ---------------- kInit ----------------
__global__ void __launch_bounds__(256) kInit(const int* __restrict__ spark_pos,
                                             const int* __restrict__ spark_age) {
  int t = threadIdx.x;
  for (int j = t; j < N; j += 256) g_forced[j] = 0;
  __syncthreads();

  const unsigned B0 = 0u, B1 = 42u;
  unsigned kexp0, kexp1, krand0, krand1, kcat0, kcat1;
  keypair(B0, B1, 1u, kexp0, kexp1);
  keypair(B0, B1, 2u, krand0, krand1);
  keypair(B0, B1, 3u, kcat0, kcat1);

  int i = t;
  unsigned ke0, ke1;
  keypair(kexp0, kexp1, (unsigned)i, ke0, ke1);
  g_explore[i] = (f01(bits32(ke0, ke1, 0u)) < 0.05f) ? 1 : 0;
  unsigned kr0, kr1, k20, k21;
  keypair(krand0, krand1, (unsigned)i, kr0, kr1);
  keypair(kr0, kr1, 1u, k20, k21);
  g_randpos[i] = (int)(bits32(k20, k21, 0u) & (unsigned)(N - 1));
  unsigned kc0, kc1;
  keypair(kcat0, kcat1, (unsigned)i, kc0, kc1);
  g_kc0[i] = kc0;
  g_kc1[i] = kc1;
  if (spark_age[i] < 5) g_forced[spark_pos[i]] = 1;
}

// ---------------- kMdec ----------------
__global__ void __launch_bounds__(1024) kMdec(const float* __restrict__ M_in) {
  int t = blockIdx.x * 1024 + threadIdx.x;
  g_Mdec[t] = __fmul_rn(M_in[t], 0.95f);
}

// ---------------- kMV: matvec + W decay/clip + compact column copy --------
__global__ void __launch_bounds__(256) kMV(const float* __restrict__ W,
                                           const float* __restrict__ s_in,
                                           float* __restrict__ outW) {
  int r = blockIdx.x;
  const float4* w4 = (const float4*)(W + (size_t)r * N);
  const float4* s4 = (const float4*)s_in;
  float4* o4 = (float4*)(outW + (size_t)r * N);
  float4* wc4 = (float4*)(g_Wc + (size_t)r * 256);
  float acc = 0.f;
  for (int k = threadIdx.x; k < N / 4; k += 256) {
    float4 w = w4[k];
    float4 sv = s4[k];
    acc += w.x * (sv.x * 0.95f) + w.y * (sv.y * 0.95f)
         + w.z * (sv.z * 0.95f) + w.w * (sv.w * 0.95f);
    if (k < 64) wc4[k] = w;                 // original W[:,0:256] slice
    float4 o;
    o.x = fminf(fmaxf(__fmul_rn(w.x, 0.999f), -2.f), 2.f);
    o.y = fminf(fmaxf(__fmul_rn(w.y, 0.999f), -2.f), 2.f);
    o.z = fminf(fmaxf(__fmul_rn(w.z, 0.999f), -2.f), 2.f);
    o.w = fminf(fmaxf(__fmul_rn(w.w, 0.999f), -2.f), 2.f);
    o4[k] = o;
  }
  for (int off = 16; off; off >>= 1) acc += __shfl_down_sync(0xffffffffu, acc, off);
  __shared__ float sred[8];
  if ((threadIdx.x & 31) == 0) sred[threadIdx.x >> 5] = acc;
  __syncthreads();
  if (threadIdx.x == 0) {
    float a = 0.f;
    for (int w = 0; w < 8; w++) a += sred[w];
    g_Ws[r] = a;
  }
}

// ---------------- kState ----------------
__device__ __forceinline__ void state_one(int j, unsigned b) {
  const float LO = __int_as_float(0xBF7FFFFF);
  const float SQ2 = __int_as_float(0x3FB504F3);
  float f = f01(b);
  float u = fmaxf(LO, __fadd_rn(__fmul_rn(f, 2.0f), LO));
  float nrm = __fmul_rn(SQ2, erfinv_xla(u));
  float noise = __fmul_rn(0.05f, nrm);
  float x = __fadd_rn(g_Ws[j], noise);
  g_sState[j] = g_forced[j] ? 1.0f : (1.0f / (1.0f + expf(-x)));
}

__global__ void __launch_bounds__(512) kState() {
  int t = blockIdx.x * 512 + threadIdx.x;
  const unsigned B0 = 0u, B1 = 42u;
  unsigned n0, n1;
  keypair(B0, B1, 0u, n0, n1);
  state_one(t,        bits32(n0, n1, (unsigned)t));
  state_one(t + 4096, bits32(n0, n1, (unsigned)(t + 4096)));
}

// ---------------- kGum: gumbels + {g,dv} store + top-32 selection ----------
__global__ void __launch_bounds__(1024) kGum(const float* __restrict__ W,
                                             const int* __restrict__ spark_pos) {
  extern __shared__ u64 sm_keys[];          // N keys = 64KB
  __shared__ u64 sm_red[32];
  __shared__ u64 sm_win;
  int i = blockIdx.x;
  int row = spark_pos[i];
  unsigned kc0 = g_kc0[i], kc1 = g_kc1[i];
  const float* wrow = W + (size_t)row * N;
  size_t base = (size_t)i * N;
  int tid = threadIdx.x;

  for (int j = tid; j < N; j += 1024) {
    unsigned b = bits32(kc0, kc1, (unsigned)j);
    float u = fmaxf(f01(b), 1.17549435e-38f);
    float g = -__nv_logf(-__nv_logf(u));
    float dv = divf(wrow[j]);
    float z0 = zf(g, dv, g_Mdec[j]);
    g_gd[base + j] = make_float2(g, dv);
    sm_keys[j] = packz(z0, j);
  }
  __syncthreads();

  u64 tmax = 0;
  #pragma unroll
  for (int t = 0; t < 8; t++) {
    u64 k = sm_keys[tid + t * 1024];
    if (k > tmax) tmax = k;
  }
  for (int rd = 0; rd < TOPT; rd++) {
    u64 v = tmax;
    for (int o = 16; o; o >>= 1) {
      u64 x = __shfl_down_sync(0xffffffffu, v, o);
      if (x > v) v = x;
    }
    if ((tid & 31) == 0) sm_red[tid >> 5] = v;
    __syncthreads();
    if (tid < 32) {
      u64 w = sm_red[tid];
      for (int o = 16; o; o >>= 1) {
        u64 x = __shfl_down_sync(0xffffffffu, w, o);
        if (x > w) w = x;
      }
      if (tid == 0) { sm_win = w; g_top[(size_t)i * TOPT + rd] = w; }
    }
    __syncthreads();
    u64 w = sm_win;
    if (tmax == w) {     // unique owner (keys unique)
      tmax = 0;
      #pragma unroll
      for (int t = 0; t < 8; t++) {
        int j = tid + t * 1024;
        u64 kk = sm_keys[j];
        if (kk == w) { sm_keys[j] = 0; kk = 0; }
        if (kk > tmax) tmax = kk;
      }
    }
  }
}

// ---------------- kScan: 256 serial iterations, block-parallel dirty -------
// smem: s[N] M[N] pnew[N] c[N] (128KB) + top[K*32] (64KB) + small
#define SMEM_SCAN (4 * N * 4 + K * TOPT * 8 + 32 * 8 + 768 * 4 + 8 * K * 4 + 64)

__global__ void __launch_bounds__(1024) kScan(const float* __restrict__ W,
                                              const int* __restrict__ sp,
                                              const float* __restrict__ se,
                                              const int* __restrict__ sa,
                                              float* __restrict__ out) {
  extern __shared__ __align__(16) unsigned char smraw[];
  float* s_sh = (float*)smraw;
  float* M_sh = s_sh + N;
  float* pnew = M_sh + N;
  int*   c_sh = (int*)(pnew + N);
  u64*   top_sh = (u64*)(c_sh + N);   // K*TOPT
  u64*   red = top_sh + K * TOPT;     // 32
  int*   dlist = (int*)(red + 32);    // 768
  int*   sp_sh = dlist + 768;         // K
  float* se_sh = (float*)(sp_sh + K);
  int*   sa_sh = (int*)(se_sh + K);
  int*   ex_sh = sa_sh + K;
  int*   rp_sh = ex_sh + K;
  int*   res_pos = rp_sh + K;
  float* res_e = (float*)(res_pos + K);
  int*   res_age = (int*)(res_e + K);
  __shared__ int nd_sh;

  int tid = threadIdx.x;
  for (int j = tid; j < N; j += 1024) {
    s_sh[j] = g_sState[j];
    M_sh[j] = g_Mdec[j];
    c_sh[j] = 0;
    pnew[j] = 0.f;
  }
  for (int t = tid; t < K * TOPT; t += 1024) top_sh[t] = g_top[t];
  if (tid < K) {
    sp_sh[tid] = sp[tid];
    se_sh[tid] = se[tid];
    sa_sh[tid] = sa[tid];
    ex_sh[tid] = g_explore[tid];
    rp_sh[tid] = g_randpos[tid];
  }
  if (tid == 0) nd_sh = 0;
  __syncthreads();

  int nd = 0;
  const unsigned FULL = 0xffffffffu;
  for (int i = 0; i < K; i++) {
    int r = sp_sh[i];
    size_t base = (size_t)i * N;

    // phase A: exact recompute at dirty positions (one per thread)
    u64 pk = 0;
    if (tid < nd) {
      int idx = dlist[tid];
      int c = c_sh[idx];
      float2 gd = g_gd[base + idx];
      float dv = ((c & 0xffff) == (r + 1)) ? divf(pnew[idx]) : gd.y;
      pk = packz(zf(gd.x, dv, M_sh[idx]), idx);
    }
    for (int o = 16; o; o >>= 1) {
      u64 v = __shfl_down_sync(FULL, pk, o);
      if (v > pk) pk = v;
    }
    if ((tid & 31) == 0) red[tid >> 5] = pk;
    __syncthreads();

    // phase B: warp 0 picks winner, lane 0 applies the update
    if (tid < 32) {
      u64 dmax = red[tid];
      for (int o = 16; o; o >>= 1) {
        u64 v = __shfl_xor_sync(FULL, dmax, o);
        if (v > dmax) dmax = v;
      }
      u64 cnd = top_sh[i * TOPT + tid];   // sorted desc
      int cidx = (N - 1) - (int)(unsigned)(cnd & 0xffffffffu);
      bool clean = !(c_sh[cidx] & BIT_LST);
      unsigned mk = __ballot_sync(FULL, clean);
      u64 best;
      if (mk) {
        best = __shfl_sync(FULL, cnd, __ffs(mk) - 1);
        if (dmax > best) best = dmax;
      } else {
        u64 last = __shfl_sync(FULL, cnd, TOPT - 1);
        if (dmax > last) {
          best = dmax;                     // clean max <= last < dmax
        } else {
          // exact full-row fallback (not expected to trigger)
          u64 fb = 0;
          for (int j = tid; j < N; j += 32) {
            int c = c_sh[j];
            float2 gd = g_gd[base + j];
            float dv = ((c & 0xffff) == (r + 1)) ? divf(pnew[j]) : gd.y;
            u64 p2 = packz(zf(gd.x, dv, M_sh[j]), j);
            if (p2 > fb) fb = p2;
          }
          for (int o = 16; o; o >>= 1) {
            u64 v = __shfl_xor_sync(FULL, fb, o);
            if (v > fb) fb = v;
          }
          best = fb;
        }
      }

      if (tid == 0) {
        int cat = (N - 1) - (int)(unsigned)(best & 0xffffffffu);
        int nxt = ex_sh[i] ? rp_sh[i] : cat;
        int prev = r;
        int cp = c_sh[prev];
        float wold = ((cp & 0xffff) == (nxt + 1))
                   ? pnew[prev]
                   : (prev < 256 ? g_Wc[(size_t)nxt * 256 + prev]
                                 : W[(size_t)nxt * N + prev]);
        pnew[prev] = __fadd_rn(__fmul_rn(wold, 0.95f),
                               __fmul_rn(s_sh[prev], 0.05f));
        int ncp = (cp & ~0xffff) | (nxt + 1);
        if (!(cp & BIT_LST)) { dlist[nd] = prev; nd++; ncp |= BIT_LST; }
        c_sh[prev] = ncp;
        int cn = c_sh[nxt];                 // after prev write (nxt may == prev)
        M_sh[nxt] = __fadd_rn(M_sh[nxt], 0.2f);
        int ncn = cn | BIT_DEP;
        if (!(cn & BIT_LST)) { dlist[nd] = nxt; nd++; ncn |= BIT_LST; }
        c_sh[nxt] = ncn;
        float e = __fmul_rn(se_sh[i], 0.98f);
        s_sh[nxt] = e;
        int age = sa_sh[i] + 1;
        int pos = nxt;
        if (e < 0.05f) { pos = i % N; e = 1.0f; age = 0; }
        res_pos[i] = pos;
        res_e[i] = e;
        res_age[i] = age;
        nd_sh = nd;
      }
    }
    __syncthreads();
    nd = nd_sh;
  }

  // epilogue: outputs (layout: pos[K], W[N*N], s[N], M[N], energy[K], age[K])
  const size_t OUT_W = K;
  const size_t OUT_S = OUT_W + (size_t)N * N;
  const size_t OUT_M = OUT_S + N;
  const size_t OUT_E = OUT_M + N;
  const size_t OUT_A = OUT_E + K;
  for (int j = tid; j < N; j += 1024) {
    out[OUT_S + j] = s_sh[j];
    out[OUT_M + j] = M_sh[j];
    int c = c_sh[j];
    int prow = c & 0xffff;
    if (prow) {
      size_t idx = (size_t)(prow - 1) * N + (size_t)j;
      out[OUT_W + idx] = fminf(fmaxf(__fmul_rn(pnew[j], 0.999f), -2.f), 2.f);
    }
  }
  for (int i2 = tid; i2 < K; i2 += 1024) {
    out[i2] = (float)res_pos[i2];
    out[OUT_E + i2] = res_e[i2];
    out[OUT_A + i2] = (float)res_age[i2];
  }
}

// ---------------- launch ----------------
extern "C" void kernel_launch(void* const* d_in, const int* in_sizes, int n_in,
                              void* d_out, int out_size) {
  const float* W = (const float*)d_in[0];
  const float* s = (const float*)d_in[1];
  const float* M = (const float*)d_in[2];
  const int* sp = (const int*)d_in[3];
  const float* se = (const float*)d_in[4];
  const int* sa = (const int*)d_in[5];
  float* out = (float*)d_out;

  cudaFuncSetAttribute(kGum, cudaFuncAttributeMaxDynamicSharedMemorySize,
                       N * 8);
  cudaFuncSetAttribute(kScan, cudaFuncAttributeMaxDynamicSharedMemorySize,
                       SMEM_SCAN);

  kInit<<<1, 256>>>(sp, sa);
  kMdec<<<8, 1024>>>(M);
  kMV<<<N, 256>>>(W, s, out + K);      // out_W starts right after pos[K]
  kState<<<8, 512>>>();
  kGum<<<K, 1024, N * 8>>>(W, sp);
  kScan<<<1, 1024, SMEM_SCAN>>>(W, sp, se, sa, out);
}

// round 10
// speedup vs baseline: 2.4408x; 1.0096x over previous
#include <cuda_runtime.h>
#include <stdint.h>
#include <stddef.h>

// SparkFieldNet single step, bit-matching JAX threefry-2x32 RNG
// (jax_threefry_partitionable scheme).
// Inputs: 0=W[N*N] f32, 1=s[N] f32, 2=M[N] f32, 3=spark_pos[K] i32,
//         4=spark_energy[K] f32, 5=spark_age[K] i32
// Output: concat(pos[K], W[N*N], s[N], M[N], energy[K], age[K]) as float32.

#define N 8192
#define K 256
#define TOPT 32
#define BIT_DEP (1 << 16)
#define BIT_LST (1 << 17)

extern "C" __device__ float __nv_logf(float);

typedef unsigned long long u64;

// ---- device scratch ----
__device__ float2 g_gd[(size_t)K * N];   // {gumbel, div} per spark x pos (16MB)
__device__ float  g_Wc[(size_t)N * 256]; // W[:, 0:256] compact copy (8MB)
__device__ u64    g_top[(size_t)K * TOPT];
__device__ float  g_Ws[N];
__device__ float  g_sState[N];
__device__ float  g_Mdec[N];
__device__ int    g_forced[N];
__device__ unsigned g_kc0[K], g_kc1[K];
__device__ int    g_explore[K];
__device__ int    g_randpos[K];

// ---------------- Threefry-2x32 (JAX-exact, 20 rounds) ----------------
__device__ __forceinline__ void tf2x32(unsigned k0, unsigned k1,
                                       unsigned x0, unsigned x1,
                                       unsigned& o0, unsigned& o1) {
  unsigned ks2 = k0 ^ k1 ^ 0x1BD11BDAu;
  x0 += k0; x1 += k1;
#define TFR(r) { x0 += x1; x1 = (x1 << (r)) | (x1 >> (32 - (r))); x1 ^= x0; }
  TFR(13) TFR(15) TFR(26) TFR(6)   x0 += k1;  x1 += ks2 + 1u;
  TFR(17) TFR(29) TFR(16) TFR(24)  x0 += ks2; x1 += k0 + 2u;
  TFR(13) TFR(15) TFR(26) TFR(6)   x0 += k0;  x1 += k1 + 3u;
  TFR(17) TFR(29) TFR(16) TFR(24)  x0 += k1;  x1 += ks2 + 4u;
  TFR(13) TFR(15) TFR(26) TFR(6)   x0 += ks2; x1 += k0 + 5u;
#undef TFR
  o0 = x0; o1 = x1;
}

__device__ __forceinline__ void keypair(unsigned k0, unsigned k1, unsigned i,
                                        unsigned& o0, unsigned& o1) {
  tf2x32(k0, k1, 0u, i, o0, o1);
}

__device__ __forceinline__ unsigned bits32(unsigned k0, unsigned k1, unsigned j) {
  unsigned o0, o1;
  tf2x32(k0, k1, 0u, j, o0, o1);
  return o0 ^ o1;
}

__device__ __forceinline__ float f01(unsigned b) {
  return __fadd_rn(__uint_as_float((b >> 9) | 0x3f800000u), -1.0f);
}

__device__ __forceinline__ u64 packz(float z, int j) {
  unsigned zu = __float_as_uint(z);
  zu = (zu & 0x80000000u) ? ~zu : (zu | 0x80000000u);
  return ((u64)zu << 32) | (unsigned)(N - 1 - j);   // tie -> smaller index wins
}

__device__ __forceinline__ float divf(float w) {
  return __fdiv_rn(__fadd_rn(fmaxf(w, 0.0f), 1e-6f), 0.3f);
}

__device__ __forceinline__ float zf(float g, float dv, float m) {
  return __fadd_rn(g, __fadd_rn(dv, __fmul_rn(0.8f, m)));
}

// discard-load to warm L1 (not eliminable by the compiler)
__device__ __forceinline__ void warm64(const void* p) {
  u64 d;
  asm volatile("ld.global.nc.b64 %0, [%1];" : "=l"(d) : "l"(p));
}

// XLA ErfInv f32 polynomial (Giles)
__device__ __forceinline__ float erfinv_xla(float x) {
  float w = -log1pf(-__fmul_rn(x, x));
  float p;
  if (w < 5.0f) {
    w = w - 2.5f;
    p = 2.81022636e-08f;
    p = fmaf(p, w, 3.43273939e-07f);
    p = fmaf(p, w, -3.5233877e-06f);
    p = fmaf(p, w, -4.39150654e-06f);
    p = fmaf(p, w, 0.00021858087f);
    p = fmaf(p, w, -0.00125372503f);
    p = fmaf(p, w, -0.00417768164f);
    p = fmaf(p, w, 0.246640727f);
    p = fmaf(p, w, 1.50140941f);
  } else {
    w = sqrtf(w) - 3.0f;
    p = -0.000200214257f;
    p = fmaf(p, w, 0.000100950558f);
    p = fmaf(p, w, 0.00134934322f);
    p = fmaf(p, w, -0.00367342844f);
    p = fmaf(p, w, 0.00573950773f);
    p = fmaf(p, w, -0.0076224613f);
    p = fmaf(p, w, 0.00943887047f);
    p = fmaf(p, w, 1.00167406f);
    p = fmaf(p, w, 2.83297682f);
  }
  return p * x;
}

// ---------------- kInit ----------------
__global__ void __launch_bounds__(256) kInit(const int* __restrict__ spark_pos,
                                             const int* __restrict__ spark_age) {
  int t = threadIdx.x;
  for (int j = t; j < N; j += 256) g_forced[j] = 0;
  __syncthreads();

  const unsigned B0 = 0u, B1 = 42u;
  unsigned kexp0, kexp1, krand0, krand1, kcat0, kcat1;
  keypair(B0, B1, 1u, kexp0, kexp1);
  keypair(B0, B1, 2u, krand0, krand1);
  keypair(B0, B1, 3u, kcat0, kcat1);

  int i = t;
  unsigned ke0, ke1;
  keypair(kexp0, kexp1, (unsigned)i, ke0, ke1);
  g_explore[i] = (f01(bits32(ke0, ke1, 0u)) < 0.05f) ? 1 : 0;
  unsigned kr0, kr1, k20, k21;
  keypair(krand0, krand1, (unsigned)i, kr0, kr1);
  keypair(kr0, kr1, 1u, k20, k21);
  g_randpos[i] = (int)(bits32(k20, k21, 0u) & (unsigned)(N - 1));
  unsigned kc0, kc1;
  keypair(kcat0, kcat1, (unsigned)i, kc0, kc1);
  g_kc0[i] = kc0;
  g_kc1[i] = kc1;
  if (spark_age[i] < 5) g_forced[spark_pos[i]] = 1;
}

// ---------------- kMdec ----------------
__global__ void __launch_bounds__(1024) kMdec(const float* __restrict__ M_in) {
  int t = blockIdx.x * 1024 + threadIdx.x;
  g_Mdec[t] = __fmul_rn(M_in[t], 0.95f);
}

// ---------------- kMV: matvec + W decay/clip + compact column copy --------
__global__ void __launch_bounds__(256) kMV(const float* __restrict__ W,
                                           const float* __restrict__ s_in,
                                           float* __restrict__ outW) {
  int r = blockIdx.x;
  const float4* w4 = (const float4*)(W + (size_t)r * N);
  const float4* s4 = (const float4*)s_in;
  float4* o4 = (float4*)(outW + (size_t)r * N);
  float4* wc4 = (float4*)(g_Wc + (size_t)r * 256);
  float acc = 0.f;
  for (int k = threadIdx.x; k < N / 4; k += 256) {
    float4 w = w4[k];
    float4 sv = s4[k];
    acc += w.x * (sv.x * 0.95f) + w.y * (sv.y * 0.95f)
         + w.z * (sv.z * 0.95f) + w.w * (sv.w * 0.95f);
    if (k < 64) wc4[k] = w;                 // original W[:,0:256] slice
    float4 o;
    o.x = fminf(fmaxf(__fmul_rn(w.x, 0.999f), -2.f), 2.f);
    o.y = fminf(fmaxf(__fmul_rn(w.y, 0.999f), -2.f), 2.f);
    o.z = fminf(fmaxf(__fmul_rn(w.z, 0.999f), -2.f), 2.f);
    o.w = fminf(fmaxf(__fmul_rn(w.w, 0.999f), -2.f), 2.f);
    o4[k] = o;
  }
  for (int off = 16; off; off >>= 1) acc += __shfl_down_sync(0xffffffffu, acc, off);
  __shared__ float sred[8];
  if ((threadIdx.x & 31) == 0) sred[threadIdx.x >> 5] = acc;
  __syncthreads();
  if (threadIdx.x == 0) {
    float a = 0.f;
    for (int w = 0; w < 8; w++) a += sred[w];
    g_Ws[r] = a;
  }
}

// ---------------- kState ----------------
__device__ __forceinline__ void state_one(int j, unsigned b) {
  const float LO = __int_as_float(0xBF7FFFFF);
  const float SQ2 = __int_as_float(0x3FB504F3);
  float f = f01(b);
  float u = fmaxf(LO, __fadd_rn(__fmul_rn(f, 2.0f), LO));
  float nrm = __fmul_rn(SQ2, erfinv_xla(u));
  float noise = __fmul_rn(0.05f, nrm);
  float x = __fadd_rn(g_Ws[j], noise);
  g_sState[j] = g_forced[j] ? 1.0f : (1.0f / (1.0f + expf(-x)));
}

__global__ void __launch_bounds__(512) kState() {
  int t = blockIdx.x * 512 + threadIdx.x;
  const unsigned B0 = 0u, B1 = 42u;
  unsigned n0, n1;
  keypair(B0, B1, 0u, n0, n1);
  state_one(t,        bits32(n0, n1, (unsigned)t));
  state_one(t + 4096, bits32(n0, n1, (unsigned)(t + 4096)));
}

// ---------------- kGum: gumbels + {g,dv} store + top-32 selection ----------
__global__ void __launch_bounds__(1024) kGum(const float* __restrict__ W,
                                             const int* __restrict__ spark_pos) {
  extern __shared__ u64 sm_keys[];          // N keys = 64KB
  __shared__ u64 sm_red[32];
  __shared__ u64 sm_win;
  int i = blockIdx.x;
  int row = spark_pos[i];
  unsigned kc0 = g_kc0[i], kc1 = g_kc1[i];
  const float* wrow = W + (size_t)row * N;
  size_t base = (size_t)i * N;
  int tid = threadIdx.x;

  for (int j = tid; j < N; j += 1024) {
    unsigned b = bits32(kc0, kc1, (unsigned)j);
    float u = fmaxf(f01(b), 1.17549435e-38f);
    float g = -__nv_logf(-__nv_logf(u));
    float dv = divf(wrow[j]);
    float z0 = zf(g, dv, g_Mdec[j]);
    g_gd[base + j] = make_float2(g, dv);
    sm_keys[j] = packz(z0, j);
  }
  __syncthreads();

  u64 tmax = 0;
  #pragma unroll
  for (int t = 0; t < 8; t++) {
    u64 k = sm_keys[tid + t * 1024];
    if (k > tmax) tmax = k;
  }
  for (int rd = 0; rd < TOPT; rd++) {
    u64 v = tmax;
    for (int o = 16; o; o >>= 1) {
      u64 x = __shfl_down_sync(0xffffffffu, v, o);
      if (x > v) v = x;
    }
    if ((tid & 31) == 0) sm_red[tid >> 5] = v;
    __syncthreads();
    if (tid < 32) {
      u64 w = sm_red[tid];
      for (int o = 16; o; o >>= 1) {
        u64 x = __shfl_down_sync(0xffffffffu, w, o);
        if (x > w) w = x;
      }
      if (tid == 0) { sm_win = w; g_top[(size_t)i * TOPT + rd] = w; }
    }
    __syncthreads();
    u64 w = sm_win;
    if (tmax == w) {     // unique owner (keys unique)
      tmax = 0;
      #pragma unroll
      for (int t = 0; t < 8; t++) {
        int j = tid + t * 1024;
        u64 kk = sm_keys[j];
        if (kk == w) { sm_keys[j] = 0; kk = 0; }
        if (kk > tmax) tmax = kk;
      }
    }
  }
}

// ---------------- kScan: 256 serial iterations, pipelined ------------------
// smem: s[N] M[N] pnew[N] c[N] (128KB) + top[K*32] (64KB) + small
#define SMEM_SCAN (4 * N * 4 + K * TOPT * 8 + 16 * 8 + 768 * 4 + 8 * K * 4 + 64)

__global__ void __launch_bounds__(512) kScan(const float* __restrict__ W,
                                             const int* __restrict__ sp,
                                             const float* __restrict__ se,
                                             const int* __restrict__ sa,
                                             float* __restrict__ out) {
  extern __shared__ __align__(16) unsigned char smraw[];
  float* s_sh = (float*)smraw;
  float* M_sh = s_sh + N;
  float* pnew = M_sh + N;
  int*   c_sh = (int*)(pnew + N);
  u64*   top_sh = (u64*)(c_sh + N);   // K*TOPT
  u64*   red = top_sh + K * TOPT;     // 16
  int*   dlist = (int*)(red + 16);    // 768
  int*   sp_sh = dlist + 768;         // K
  float* se_sh = (float*)(sp_sh + K);
  int*   sa_sh = (int*)(se_sh + K);
  int*   ex_sh = sa_sh + K;
  int*   rp_sh = ex_sh + K;
  int*   res_pos = rp_sh + K;
  float* res_e = (float*)(res_pos + K);
  int*   res_age = (int*)(res_e + K);
  __shared__ int nd_sh;

  int tid = threadIdx.x;
  for (int j = tid; j < N; j += 512) {
    s_sh[j] = g_sState[j];
    M_sh[j] = g_Mdec[j];
    c_sh[j] = 0;
    pnew[j] = 0.f;
  }
  for (int t = tid; t < K * TOPT; t += 512) top_sh[t] = g_top[t];
  if (tid < K) {
    sp_sh[tid] = sp[tid];
    se_sh[tid] = se[tid];
    sa_sh[tid] = sa[tid];
    ex_sh[tid] = g_explore[tid];
    rp_sh[tid] = g_randpos[tid];
  }
  if (tid == 0) nd_sh = 0;
  __syncthreads();

  int nd = 0;        // dirty count valid at iteration start
  int ndpref = 0;    // slots with `pre` prefetched for this iteration
  float2 pre = make_float2(0.f, 0.f);
  const unsigned FULL = 0xffffffffu;

  for (int i = 0; i < K; i++) {
    int r = sp_sh[i];
    size_t base = (size_t)i * N;

    // ---- phase A: exact recompute at dirty positions (one per thread) ----
    u64 pk = 0;
    if (tid < nd) {
      int idx = dlist[tid];
      float2 gd = (tid < ndpref) ? pre : g_gd[base + idx];  // fresh = L1-warmed
      int c = c_sh[idx];
      float dv = ((c & 0xffff) == (r + 1)) ? divf(pnew[idx]) : gd.y;
      pk = packz(zf(gd.x, dv, M_sh[idx]), idx);
    }
    for (int o = 16; o; o >>= 1) {
      u64 v = __shfl_down_sync(FULL, pk, o);
      if (v > pk) pk = v;
    }
    if ((tid & 31) == 0) red[tid >> 5] = pk;
    // prefetch g_gd for next iteration's existing dirty slots
    if (i + 1 < K && tid < nd) pre = g_gd[base + N + dlist[tid]];
    int ndpref_next = nd;
    __syncthreads();

    // ---- phase B: warp 0 picks winner, lane 0 applies the update ----
    if (tid < 32) {
      int lane = tid;
      int prev = r;
      int rp = rp_sh[i];
      u64 cnd = top_sh[i * TOPT + lane];   // sorted desc
      int cidx = (N - 1) - (int)(unsigned)(cnd & 0xffffffffu);
      // speculative wold loads (overlap with reduction below)
      float wc = 0.f, wrp = 0.f;
      if (prev < 256) {
        wc = g_Wc[(size_t)cidx * 256 + prev];
        if (lane == 1) wrp = g_Wc[(size_t)rp * 256 + prev];
      }
      // warm next-iter g_gd lines for potential new dirty slots
      if (i + 1 < K) {
        warm64(&g_gd[base + N + cidx]);
        if (lane == 0) warm64(&g_gd[base + N + prev]);
        if (lane == 1) warm64(&g_gd[base + N + rp]);
      }

      u64 dmax = (lane < 16) ? red[lane] : 0;
      for (int o = 16; o; o >>= 1) {
        u64 v = __shfl_xor_sync(FULL, dmax, o);
        if (v > dmax) dmax = v;
      }

      bool clean = !(c_sh[cidx] & BIT_LST);
      unsigned mk = __ballot_sync(FULL, clean);
      int Lwin = mk ? (__ffs(mk) - 1) : 0;
      u64 best;
      bool cleanWin = false;
      if (mk) {
        u64 bc = __shfl_sync(FULL, cnd, Lwin);
        if (dmax > bc) { best = dmax; } else { best = bc; cleanWin = true; }
      } else {
        u64 last = __shfl_sync(FULL, cnd, TOPT - 1);
        if (dmax > last) {
          best = dmax;                     // clean max <= last < dmax
        } else {
          // exact full-row fallback (not expected to trigger)
          u64 fb = 0;
          for (int j = lane; j < N; j += 32) {
            int c = c_sh[j];
            float2 gd = g_gd[base + j];
            float dv = ((c & 0xffff) == (r + 1)) ? divf(pnew[j]) : gd.y;
            u64 p2 = packz(zf(gd.x, dv, M_sh[j]), j);
            if (p2 > fb) fb = p2;
          }
          for (int o = 16; o; o >>= 1) {
            u64 v = __shfl_xor_sync(FULL, fb, o);
            if (v > fb) fb = v;
          }
          best = fb;
        }
      }
      float wcL  = __shfl_sync(FULL, wc, Lwin);
      float wrpB = __shfl_sync(FULL, wrp, 1);

      if (lane == 0) {
        int cat = (N - 1) - (int)(unsigned)(best & 0xffffffffu);
        int ex = ex_sh[i];
        int nxt = ex ? rp : cat;
        int cp = c_sh[prev];
        float wold;
        if ((cp & 0xffff) == (nxt + 1)) {
          wold = pnew[prev];
        } else if (ex) {
          wold = (prev < 256) ? wrpB : W[(size_t)nxt * N + prev];
        } else if (cleanWin) {
          wold = (prev < 256) ? wcL : W[(size_t)nxt * N + prev];
        } else {
          wold = (prev < 256) ? g_Wc[(size_t)nxt * 256 + prev]
                              : W[(size_t)nxt * N + prev];
        }
        pnew[prev] = __fadd_rn(__fmul_rn(wold, 0.95f),
                               __fmul_rn(s_sh[prev], 0.05f));
        int ndl = nd;
        int ncp = (cp & ~0xffff) | (nxt + 1);
        if (!(cp & BIT_LST)) { dlist[ndl] = prev; ndl++; ncp |= BIT_LST; }
        c_sh[prev] = ncp;
        int cn = c_sh[nxt];                 // after prev write (nxt may == prev)
        M_sh[nxt] = __fadd_rn(M_sh[nxt], 0.2f);
        int ncn = cn | BIT_DEP;
        if (!(cn & BIT_LST)) { dlist[ndl] = nxt; ndl++; ncn |= BIT_LST; }
        c_sh[nxt] = ncn;
        float e = __fmul_rn(se_sh[i], 0.98f);
        s_sh[nxt] = e;
        int age = sa_sh[i] + 1;
        int pos = nxt;
        if (e < 0.05f) { pos = i % N; e = 1.0f; age = 0; }
        res_pos[i] = pos;
        res_e[i] = e;
        res_age[i] = age;
        nd_sh = ndl;
      }
    }
    __syncthreads();
    nd = nd_sh;
    ndpref = ndpref_next;
  }

  // epilogue: outputs (layout: pos[K], W[N*N], s[N], M[N], energy[K], age[K])
  const size_t OUT_W = K;
  const size_t OUT_S = OUT_W + (size_t)N * N;
  const size_t OUT_M = OUT_S + N;
  const size_t OUT_E = OUT_M + N;
  const size_t OUT_A = OUT_E + K;
  for (int j = tid; j < N; j += 512) {
    out[OUT_S + j] = s_sh[j];
    out[OUT_M + j] = M_sh[j];
    int c = c_sh[j];
    int prow = c & 0xffff;
    if (prow) {
      size_t idx = (size_t)(prow - 1) * N + (size_t)j;
      out[OUT_W + idx] = fminf(fmaxf(__fmul_rn(pnew[j], 0.999f), -2.f), 2.f);
    }
  }
  for (int i2 = tid; i2 < K; i2 += 512) {
    out[i2] = (float)res_pos[i2];
    out[OUT_E + i2] = res_e[i2];
    out[OUT_A + i2] = (float)res_age[i2];
  }
}

// ---------------- launch ----------------
extern "C" void kernel_launch(void* const* d_in, const int* in_sizes, int n_in,
                              void* d_out, int out_size) {
  const float* W = (const float*)d_in[0];
  const float* s = (const float*)d_in[1];
  const float* M = (const float*)d_in[2];
  const int* sp = (const int*)d_in[3];
  const float* se = (const float*)d_in[4];
  const int* sa = (const int*)d_in[5];
  float* out = (float*)d_out;

  cudaFuncSetAttribute(kGum, cudaFuncAttributeMaxDynamicSharedMemorySize,
                       N * 8);
  cudaFuncSetAttribute(kScan, cudaFuncAttributeMaxDynamicSharedMemorySize,
                       SMEM_SCAN);

  kInit<<<1, 256>>>(sp, sa);
  kMdec<<<8, 1024>>>(M);
  kMV<<<N, 256>>>(W, s, out + K);      // out_W starts right after pos[K]
  kState<<<8, 512>>>();
  kGum<<<K, 1024, N * 8>>>(W, sp);
  kScan<<<1, 512, SMEM_SCAN>>>(W, sp, se, sa, out);
}